// round 1
// baseline (speedup 1.0000x reference)
#include <cuda_runtime.h>
#include <math.h>

#define N_NODES   50000
#define N_EDGES   800000
#define HDIM      96
#define NUM_IN    11
#define PE_DIM    24
#define N_LAYERS  4
#define N_GRAPHS  256

// ---------------- scratch (device globals; no allocations allowed) ----------
__device__ float g_h   [N_NODES * HDIM];
__device__ float g_A   [N_NODES * HDIM];   // (h @ Wa)  -> gathered by send
__device__ float g_B   [N_NODES * HDIM];   // (h @ Wb)  -> gathered by rec
__device__ float g_aggr[N_NODES * HDIM];
__device__ float g_u   [N_NODES * HDIM];
__device__ float g_dist[N_EDGES];
__device__ int   g_send[N_EDGES];
__device__ int   g_rec [N_EDGES];
__device__ float g_pooled[N_GRAPHS * HDIM];

__device__ __forceinline__ float silu_f(float v) {
    return v / (1.0f + __expf(-v));
}

__device__ __forceinline__ void red_add_v4(float* p, float4 v) {
    asm volatile("red.global.add.v4.f32 [%0], {%1,%2,%3,%4};"
                 :: "l"(p), "f"(v.x), "f"(v.y), "f"(v.z), "f"(v.w) : "memory");
}

// ---------------- edge preprocessing (indices + dist), dtype-robust ---------
__global__ void edge_prep(const int* __restrict__ eraw, const float* __restrict__ pos) {
    __shared__ int s_is64;
    if (threadIdx.x == 0) {
        // if int64: odd int32 slots are hi-words == 0 (values are small positive)
        s_is64 = ((eraw[2*N_EDGES-1] | eraw[2*N_EDGES-3] |
                   eraw[2*N_EDGES-5] | eraw[2*N_EDGES-7]) == 0) ? 1 : 0;
    }
    __syncthreads();
    int e = blockIdx.x * blockDim.x + threadIdx.x;
    if (e >= N_EDGES) return;
    int s, r;
    if (s_is64) {
        const long long* e64 = (const long long*)eraw;
        s = (int)e64[e]; r = (int)e64[N_EDGES + e];
    } else {
        s = eraw[e];     r = eraw[N_EDGES + e];
    }
    g_send[e] = s; g_rec[e] = r;
    float dx = pos[3*s+0] - pos[3*r+0];
    float dy = pos[3*s+1] - pos[3*r+1];
    float dz = pos[3*s+2] - pos[3*r+2];
    g_dist[e] = sqrtf(dx*dx + dy*dy + dz*dz);
}

// ---------------- generic node MLP layer: out = act(in1@W1 + in2@W2 + b)[+res]
// block = (24,16) = 384 thr, 64 rows/block, 4x4 register tile, H=96 outputs
__global__ void __launch_bounds__(384)
node_mlp(const float* __restrict__ in1, int K1, const float* __restrict__ W1,
         const float* __restrict__ in2, int K2, const float* __restrict__ W2,
         const float* __restrict__ bias, const float* __restrict__ res,
         float* __restrict__ out, int nrows, int do_silu)
{
    extern __shared__ float sm[];
    const int K1p = (K1 + 3) & ~3;
    const int K2p = (K2 + 3) & ~3;
    float* Ws1  = sm;
    float* Ws2  = sm + K1p * 96;
    float* sbuf = Ws2 + K2p * 96;

    const int tid  = threadIdx.y * 24 + threadIdx.x;
    const int base = blockIdx.x * 64;
    const int f0   = threadIdx.x * 4;
    const int r0   = threadIdx.y * 4;

    for (int idx = tid; idx < K1p * 96; idx += 384) {
        int k = idx / 96;
        Ws1[idx] = (k < K1) ? W1[idx] : 0.0f;
    }
    if (in2) {
        for (int idx = tid; idx < K2p * 96; idx += 384) {
            int k = idx / 96;
            Ws2[idx] = (k < K2) ? W2[idx] : 0.0f;
        }
    }

    float acc[4][4];
    #pragma unroll
    for (int i = 0; i < 4; i++)
        #pragma unroll
        for (int c = 0; c < 4; c++) acc[i][c] = 0.0f;

    // ---- phase 1: in1 @ W1 ----
    for (int idx = tid; idx < 64 * K1p; idx += 384) {
        int e = idx / K1p, k = idx - e * K1p;
        int row = base + e;
        sbuf[idx] = (k < K1 && row < nrows) ? in1[(size_t)row * K1 + k] : 0.0f;
    }
    __syncthreads();
    for (int k = 0; k < K1p; k += 4) {
        float4 wa = *(const float4*)&Ws1[(k+0)*96 + f0];
        float4 wb = *(const float4*)&Ws1[(k+1)*96 + f0];
        float4 wc = *(const float4*)&Ws1[(k+2)*96 + f0];
        float4 wd = *(const float4*)&Ws1[(k+3)*96 + f0];
        #pragma unroll
        for (int i = 0; i < 4; i++) {
            float4 tv = *(const float4*)&sbuf[(r0+i)*K1p + k];
            acc[i][0] += tv.x*wa.x + tv.y*wb.x + tv.z*wc.x + tv.w*wd.x;
            acc[i][1] += tv.x*wa.y + tv.y*wb.y + tv.z*wc.y + tv.w*wd.y;
            acc[i][2] += tv.x*wa.z + tv.y*wb.z + tv.z*wc.z + tv.w*wd.z;
            acc[i][3] += tv.x*wa.w + tv.y*wb.w + tv.z*wc.w + tv.w*wd.w;
        }
    }

    // ---- phase 2: + in2 @ W2 ----
    if (in2) {
        __syncthreads();
        for (int idx = tid; idx < 64 * K2p; idx += 384) {
            int e = idx / K2p, k = idx - e * K2p;
            int row = base + e;
            sbuf[idx] = (k < K2 && row < nrows) ? in2[(size_t)row * K2 + k] : 0.0f;
        }
        __syncthreads();
        for (int k = 0; k < K2p; k += 4) {
            float4 wa = *(const float4*)&Ws2[(k+0)*96 + f0];
            float4 wb = *(const float4*)&Ws2[(k+1)*96 + f0];
            float4 wc = *(const float4*)&Ws2[(k+2)*96 + f0];
            float4 wd = *(const float4*)&Ws2[(k+3)*96 + f0];
            #pragma unroll
            for (int i = 0; i < 4; i++) {
                float4 tv = *(const float4*)&sbuf[(r0+i)*K2p + k];
                acc[i][0] += tv.x*wa.x + tv.y*wb.x + tv.z*wc.x + tv.w*wd.x;
                acc[i][1] += tv.x*wa.y + tv.y*wb.y + tv.z*wc.y + tv.w*wd.y;
                acc[i][2] += tv.x*wa.z + tv.y*wb.z + tv.z*wc.z + tv.w*wd.z;
                acc[i][3] += tv.x*wa.w + tv.y*wb.w + tv.z*wc.w + tv.w*wd.w;
            }
        }
    }

    // ---- epilogue ----
    #pragma unroll
    for (int i = 0; i < 4; i++) {
        int row = base + r0 + i;
        if (row >= nrows) continue;
        float4 v;
        v.x = acc[i][0] + (bias ? bias[f0+0] : 0.0f);
        v.y = acc[i][1] + (bias ? bias[f0+1] : 0.0f);
        v.z = acc[i][2] + (bias ? bias[f0+2] : 0.0f);
        v.w = acc[i][3] + (bias ? bias[f0+3] : 0.0f);
        if (do_silu) {
            v.x = silu_f(v.x); v.y = silu_f(v.y);
            v.z = silu_f(v.z); v.w = silu_f(v.w);
        }
        if (res) {
            float4 rv = *(const float4*)&res[(size_t)row*96 + f0];
            v.x += rv.x; v.y += rv.y; v.z += rv.z; v.w += rv.w;
        }
        *(float4*)&out[(size_t)row*96 + f0] = v;
    }
}

// ---------------- fused edge message + aggregation ---------------------------
// t = silu(A[send] + B[rec] + dist*w_d + b1) ; m = silu(t@W2 + b2); aggr[rec]+=m
__global__ void __launch_bounds__(384)
edge_msg(const float* __restrict__ wl, const float* __restrict__ b1,
         const float* __restrict__ W2, const float* __restrict__ b2)
{
    extern __shared__ float sm[];
    float* W2s = sm;              // 96*96
    float* t_s = sm + 9216;       // 64*96
    float* b1s = t_s + 6144;
    float* b2s = b1s + 96;
    float* wls = b2s + 96;
    float* de  = wls + 96;        // 64
    int*   se  = (int*)(de + 64); // 64
    int*   re  = se + 64;         // 64

    const int tid  = threadIdx.y * 24 + threadIdx.x;
    const int base = blockIdx.x * 64;

    for (int idx = tid; idx < 9216; idx += 384) W2s[idx] = W2[idx];
    if (tid < 96) { b1s[tid] = b1[tid]; b2s[tid] = b2[tid]; wls[tid] = wl[tid]; }
    else if (tid < 160) {
        int j = tid - 96; int e = base + j;
        bool v = (e < N_EDGES);
        se[j] = v ? g_send[e] : 0;
        re[j] = v ? g_rec[e]  : 0;
        de[j] = v ? g_dist[e] : 0.0f;
    }
    __syncthreads();

    for (int idx = tid; idx < 6144; idx += 384) {
        int e = idx / 96, k = idx - e * 96;
        float v = g_A[(size_t)se[e]*96 + k] + g_B[(size_t)re[e]*96 + k]
                + de[e] * wls[k] + b1s[k];
        t_s[idx] = silu_f(v);
    }
    __syncthreads();

    const int f0 = threadIdx.x * 4;
    const int r0 = threadIdx.y * 4;
    float acc[4][4];
    #pragma unroll
    for (int i = 0; i < 4; i++)
        #pragma unroll
        for (int c = 0; c < 4; c++) acc[i][c] = 0.0f;

    #pragma unroll 2
    for (int k = 0; k < 96; k += 4) {
        float4 wa = *(const float4*)&W2s[(k+0)*96 + f0];
        float4 wb = *(const float4*)&W2s[(k+1)*96 + f0];
        float4 wc = *(const float4*)&W2s[(k+2)*96 + f0];
        float4 wd = *(const float4*)&W2s[(k+3)*96 + f0];
        #pragma unroll
        for (int i = 0; i < 4; i++) {
            float4 tv = *(const float4*)&t_s[(r0+i)*96 + k];
            acc[i][0] += tv.x*wa.x + tv.y*wb.x + tv.z*wc.x + tv.w*wd.x;
            acc[i][1] += tv.x*wa.y + tv.y*wb.y + tv.z*wc.y + tv.w*wd.y;
            acc[i][2] += tv.x*wa.z + tv.y*wb.z + tv.z*wc.z + tv.w*wd.z;
            acc[i][3] += tv.x*wa.w + tv.y*wb.w + tv.z*wc.w + tv.w*wd.w;
        }
    }

    #pragma unroll
    for (int i = 0; i < 4; i++) {
        int e = base + r0 + i;
        if (e >= N_EDGES) continue;
        float4 m;
        m.x = silu_f(acc[i][0] + b2s[f0+0]);
        m.y = silu_f(acc[i][1] + b2s[f0+1]);
        m.z = silu_f(acc[i][2] + b2s[f0+2]);
        m.w = silu_f(acc[i][3] + b2s[f0+3]);
        red_add_v4(&g_aggr[(size_t)re[r0+i]*96 + f0], m);
    }
}

// ---------------- zero / pooling / readout ----------------------------------
__global__ void zero_aggr_kernel() {
    int i = blockIdx.x * 1024 + threadIdx.x;
    if (i < N_NODES * HDIM) g_aggr[i] = 0.0f;
}
__global__ void zero_pooled_kernel() {
    int i = blockIdx.x * 256 + threadIdx.x;
    if (i < N_GRAPHS * HDIM) g_pooled[i] = 0.0f;
}

__global__ void pool_kernel(const float* __restrict__ h2, const int* __restrict__ braw) {
    __shared__ int s_is64;
    if (threadIdx.x == 0) {
        s_is64 = ((braw[N_NODES-1] | braw[N_NODES-3] |
                   braw[N_NODES-5] | braw[N_NODES-7]) == 0) ? 1 : 0;
    }
    __syncthreads();
    int idx = blockIdx.x * blockDim.x + threadIdx.x;
    if (idx >= N_NODES * 24) return;
    int n = idx / 24, j = idx - n * 24;
    int g = s_is64 ? (int)((const long long*)braw)[n] : braw[n];
    float4 v = *(const float4*)&h2[(size_t)n*96 + j*4];
    red_add_v4(&g_pooled[g*96 + j*4], v);
}

__global__ void readout_kernel(const float* __restrict__ w1, const float* __restrict__ b1,
                               const float* __restrict__ w2, const float* __restrict__ b2,
                               float* __restrict__ out)
{
    __shared__ float p_s[96];
    __shared__ float t_s[96];
    int g = blockIdx.x, f = threadIdx.x;
    p_s[f] = g_pooled[g*96 + f];
    __syncthreads();
    float a = b1[f];
    #pragma unroll 8
    for (int k = 0; k < 96; k++) a += p_s[k] * w1[k*96 + f];
    t_s[f] = silu_f(a) * w2[f];
    __syncthreads();
    if (f < 32) {
        float sum = t_s[f] + t_s[f+32] + t_s[f+64];
        #pragma unroll
        for (int o = 16; o > 0; o >>= 1) sum += __shfl_down_sync(0xffffffffu, sum, o);
        if (f == 0) out[g] = sum + b2[0];
    }
}

// ---------------- host launcher ----------------------------------------------
static void launch_node(const float* in1, int K1, const float* W1,
                        const float* in2, int K2, const float* W2,
                        const float* bias, const float* res,
                        float* out, int do_silu)
{
    int K1p = (K1 + 3) & ~3;
    int K2p = (K2 + 3) & ~3;
    int Kmax = K1p > K2p ? K1p : K2p;
    size_t smem = (size_t)(K1p + K2p) * 96 * 4 + (size_t)64 * Kmax * 4;
    dim3 tb(24, 16);
    int blocks = (N_NODES + 63) / 64;
    node_mlp<<<blocks, tb, smem>>>(in1, K1, W1, in2, K2, W2, bias, res, out, N_NODES, do_silu);
}

extern "C" void kernel_launch(void* const* d_in, const int* in_sizes, int n_in,
                              void* d_out, int out_size)
{
    const float* x    = (const float*)d_in[0];
    const float* pos  = (const float*)d_in[1];
    const float* pe   = (const float*)d_in[2];
    const int*   eraw = (const int*)d_in[3];
    const int*   braw = (const int*)d_in[4];
    const float* ew1  = (const float*)d_in[5];
    const float* eb1  = (const float*)d_in[6];
    const float* ew2  = (const float*)d_in[7];
    const float* eb2  = (const float*)d_in[8];
    const float* mw1  = (const float*)d_in[9];
    const float* mb1  = (const float*)d_in[10];
    const float* mw2  = (const float*)d_in[11];
    const float* mb2  = (const float*)d_in[12];
    const float* uw1  = (const float*)d_in[13];
    const float* ub1  = (const float*)d_in[14];
    const float* uw2  = (const float*)d_in[15];
    const float* ub2  = (const float*)d_in[16];
    const float* pw1  = (const float*)d_in[17];
    const float* pb1  = (const float*)d_in[18];
    const float* pw2  = (const float*)d_in[19];
    const float* pb2  = (const float*)d_in[20];
    const float* rw1  = (const float*)d_in[21];
    const float* rb1  = (const float*)d_in[22];
    const float* rw2  = (const float*)d_in[23];
    const float* rb2  = (const float*)d_in[24];
    float* out = (float*)d_out;

    float *h_, *A_, *B_, *aggr_, *u_;
    cudaGetSymbolAddress((void**)&h_,    g_h);
    cudaGetSymbolAddress((void**)&A_,    g_A);
    cudaGetSymbolAddress((void**)&B_,    g_B);
    cudaGetSymbolAddress((void**)&aggr_, g_aggr);
    cudaGetSymbolAddress((void**)&u_,    g_u);

    cudaFuncSetAttribute((const void*)node_mlp,
                         cudaFuncAttributeMaxDynamicSharedMemorySize, 100352);
    cudaFuncSetAttribute((const void*)edge_msg,
                         cudaFuncAttributeMaxDynamicSharedMemorySize, 65536);

    const size_t edge_smem = 15648u * 4 + 64u * 4 * 2 + 64u * 4; // 63360 (incl. de/se/re)

    // edges: indices + dist
    edge_prep<<<(N_EDGES + 255) / 256, 256>>>(eraw, pos);

    // embed: h = silu([x,pe]@W1+b1)@W2+b2
    launch_node(x, NUM_IN, ew1, pe, PE_DIM, ew1 + NUM_IN * 96, eb1, nullptr, u_, 1);
    launch_node(u_, 96, ew2, nullptr, 0, nullptr, eb2, nullptr, h_, 0);

    dim3 tb(24, 16);
    for (int l = 0; l < N_LAYERS; l++) {
        const float* mw1l = mw1 + (size_t)l * 193 * 96;
        const float* mb1l = mb1 + l * 96;
        const float* mw2l = mw2 + (size_t)l * 96 * 96;
        const float* mb2l = mb2 + l * 96;
        const float* uw1l = uw1 + (size_t)l * 192 * 96;
        const float* ub1l = ub1 + l * 96;
        const float* uw2l = uw2 + (size_t)l * 96 * 96;
        const float* ub2l = ub2 + l * 96;

        // A = h @ W1[0:96], B = h @ W1[96:192]
        launch_node(h_, 96, mw1l,            nullptr, 0, nullptr, nullptr, nullptr, A_, 0);
        launch_node(h_, 96, mw1l + 96 * 96,  nullptr, 0, nullptr, nullptr, nullptr, B_, 0);

        zero_aggr_kernel<<<(N_NODES * HDIM + 1023) / 1024, 1024>>>();
        edge_msg<<<N_EDGES / 64, tb, edge_smem>>>(mw1l + 192 * 96, mb1l, mw2l, mb2l);

        // u = silu(h@U1a + aggr@U1b + b1);  h = h + (u@U2 + b2)
        launch_node(h_, 96, uw1l, aggr_, 96, uw1l + 96 * 96, ub1l, nullptr, u_, 1);
        launch_node(u_, 96, uw2l, nullptr, 0, nullptr, ub2l, h_, h_, 0);
    }

    // pre-MLP -> h2 (stored in g_A)
    launch_node(h_, 96, pw1, nullptr, 0, nullptr, pb1, nullptr, u_, 1);
    launch_node(u_, 96, pw2, nullptr, 0, nullptr, pb2, nullptr, A_, 0);

    // pooled segment sum + readout
    zero_pooled_kernel<<<(N_GRAPHS * HDIM + 255) / 256, 256>>>();
    pool_kernel<<<(N_NODES * 24 + 255) / 256, 256>>>(A_, braw);
    readout_kernel<<<N_GRAPHS, 96>>>(rw1, rb1, rw2, rb2, out);
}

// round 3
// speedup vs baseline: 1.1809x; 1.1809x over previous
#include <cuda_runtime.h>
#include <math.h>

#define N_NODES   50000
#define N_EDGES   800000
#define HDIM      96
#define NUM_IN    11
#define PE_DIM    24
#define N_LAYERS  4
#define N_GRAPHS  256
#define ETILE     128

typedef unsigned long long ull;

// ---------------- scratch (device globals; no allocations allowed) ----------
__device__ float g_h   [N_NODES * HDIM];
__device__ float g_A   [N_NODES * HDIM];
__device__ float g_B   [N_NODES * HDIM];
__device__ float g_aggr[N_NODES * HDIM];
__device__ float g_u   [N_NODES * HDIM];
__device__ float g_dist[N_EDGES];
__device__ int   g_send[N_EDGES];
__device__ int   g_rec [N_EDGES];
__device__ float g_pooled[N_GRAPHS * HDIM];

__device__ __forceinline__ float silu_f(float v) {
    return v / (1.0f + __expf(-v));
}

__device__ __forceinline__ void red_add_v4(float* p, float4 v) {
    asm volatile("red.global.add.v4.f32 [%0], {%1,%2,%3,%4};"
                 :: "l"(p), "f"(v.x), "f"(v.y), "f"(v.z), "f"(v.w) : "memory");
}

// packed fp32x2 helpers (FFMA2 path — 2x fp32 FMA throughput)
__device__ __forceinline__ ull ffma2(ull a, ull b, ull c) {
    ull d;
    asm("fma.rn.f32x2 %0, %1, %2, %3;" : "=l"(d) : "l"(a), "l"(b), "l"(c));
    return d;
}
__device__ __forceinline__ ull bc2(float x) {
    ull r;
    asm("mov.b64 %0, {%1, %1};" : "=l"(r) : "f"(x));
    return r;
}
__device__ __forceinline__ float2 unpk(ull v) {
    float2 f;
    asm("mov.b64 {%0, %1}, %2;" : "=f"(f.x), "=f"(f.y) : "l"(v));
    return f;
}

// ---------------- edge preprocessing (indices + dist), dtype-robust ---------
__global__ void edge_prep(const int* __restrict__ eraw, const float* __restrict__ pos) {
    __shared__ int s_is64;
    if (threadIdx.x == 0) {
        s_is64 = ((eraw[2*N_EDGES-1] | eraw[2*N_EDGES-3] |
                   eraw[2*N_EDGES-5] | eraw[2*N_EDGES-7]) == 0) ? 1 : 0;
    }
    __syncthreads();
    int e = blockIdx.x * blockDim.x + threadIdx.x;
    if (e >= N_EDGES) return;
    int s, r;
    if (s_is64) {
        const long long* e64 = (const long long*)eraw;
        s = (int)e64[e]; r = (int)e64[N_EDGES + e];
    } else {
        s = eraw[e];     r = eraw[N_EDGES + e];
    }
    g_send[e] = s; g_rec[e] = r;
    float dx = pos[3*s+0] - pos[3*r+0];
    float dy = pos[3*s+1] - pos[3*r+1];
    float dz = pos[3*s+2] - pos[3*r+2];
    g_dist[e] = sqrtf(dx*dx + dy*dy + dz*dz);
}

// ---------------- generic node MLP layer (FFMA2) -----------------------------
// out = act(in1@W1 + in2@W2 + b)[+res]; block (24,16), 64 rows/block
__global__ void __launch_bounds__(384, 2)
node_mlp(const float* __restrict__ in1, int K1, const float* __restrict__ W1,
         const float* __restrict__ in2, int K2, const float* __restrict__ W2,
         const float* __restrict__ bias, const float* __restrict__ res,
         float* __restrict__ out, int nrows, int do_silu)
{
    extern __shared__ float sm[];
    const int K1p = (K1 + 3) & ~3;
    const int K2p = (K2 + 3) & ~3;
    float* Ws1 = sm;
    float* Ws2 = sm + K1p * 96;
    float* sT  = Ws2 + K2p * 96;   // transposed activations [K][64]

    const int tid  = threadIdx.y * 24 + threadIdx.x;
    const int base = blockIdx.x * 64;
    const int f0   = threadIdx.x * 4;
    const int r0   = threadIdx.y * 4;

    for (int idx = tid; idx < K1p * 96; idx += 384) {
        int k = idx / 96;
        Ws1[idx] = (k < K1) ? W1[idx] : 0.0f;
    }
    if (in2) {
        for (int idx = tid; idx < K2p * 96; idx += 384) {
            int k = idx / 96;
            Ws2[idx] = (k < K2) ? W2[idx] : 0.0f;
        }
    }

    ull acc[2][4];
    #pragma unroll
    for (int i = 0; i < 2; i++)
        #pragma unroll
        for (int c = 0; c < 4; c++) acc[i][c] = 0ull;

    // ---- phase 1: in1 @ W1 (transposed fill, then FFMA2 loop) ----
    if ((K1 & 3) == 0) {
        int chunks = K1 >> 2;
        for (int idx = tid; idx < 64 * chunks; idx += 384) {
            int k4 = idx / 64, e = idx - (k4 * 64);
            int row = base + e;
            float4 v = make_float4(0.f, 0.f, 0.f, 0.f);
            if (row < nrows) v = *(const float4*)&in1[(size_t)row * K1 + k4 * 4];
            sT[(k4*4+0)*64 + e] = v.x;
            sT[(k4*4+1)*64 + e] = v.y;
            sT[(k4*4+2)*64 + e] = v.z;
            sT[(k4*4+3)*64 + e] = v.w;
        }
    } else {
        for (int idx = tid; idx < 64 * K1p; idx += 384) {
            int k = idx / 64, e = idx - (k * 64);
            int row = base + e;
            sT[k*64 + e] = (k < K1 && row < nrows) ? in1[(size_t)row * K1 + k] : 0.0f;
        }
    }
    __syncthreads();
    #pragma unroll 2
    for (int k = 0; k < K1p; k++) {
        float4 w = *(const float4*)&Ws1[k*96 + f0];
        ull w0 = bc2(w.x), w1 = bc2(w.y), w2 = bc2(w.z), w3 = bc2(w.w);
        const ull* tp = (const ull*)&sT[k*64 + r0];
        #pragma unroll
        for (int ip = 0; ip < 2; ip++) {
            ull t2 = tp[ip];
            acc[ip][0] = ffma2(t2, w0, acc[ip][0]);
            acc[ip][1] = ffma2(t2, w1, acc[ip][1]);
            acc[ip][2] = ffma2(t2, w2, acc[ip][2]);
            acc[ip][3] = ffma2(t2, w3, acc[ip][3]);
        }
    }

    // ---- phase 2: + in2 @ W2 ----
    if (in2) {
        __syncthreads();
        if ((K2 & 3) == 0) {
            int chunks = K2 >> 2;
            for (int idx = tid; idx < 64 * chunks; idx += 384) {
                int k4 = idx / 64, e = idx - (k4 * 64);
                int row = base + e;
                float4 v = make_float4(0.f, 0.f, 0.f, 0.f);
                if (row < nrows) v = *(const float4*)&in2[(size_t)row * K2 + k4 * 4];
                sT[(k4*4+0)*64 + e] = v.x;
                sT[(k4*4+1)*64 + e] = v.y;
                sT[(k4*4+2)*64 + e] = v.z;
                sT[(k4*4+3)*64 + e] = v.w;
            }
        } else {
            for (int idx = tid; idx < 64 * K2p; idx += 384) {
                int k = idx / 64, e = idx - (k * 64);
                int row = base + e;
                sT[k*64 + e] = (k < K2 && row < nrows) ? in2[(size_t)row * K2 + k] : 0.0f;
            }
        }
        __syncthreads();
        #pragma unroll 2
        for (int k = 0; k < K2p; k++) {
            float4 w = *(const float4*)&Ws2[k*96 + f0];
            ull w0 = bc2(w.x), w1 = bc2(w.y), w2 = bc2(w.z), w3 = bc2(w.w);
            const ull* tp = (const ull*)&sT[k*64 + r0];
            #pragma unroll
            for (int ip = 0; ip < 2; ip++) {
                ull t2 = tp[ip];
                acc[ip][0] = ffma2(t2, w0, acc[ip][0]);
                acc[ip][1] = ffma2(t2, w1, acc[ip][1]);
                acc[ip][2] = ffma2(t2, w2, acc[ip][2]);
                acc[ip][3] = ffma2(t2, w3, acc[ip][3]);
            }
        }
    }

    // ---- epilogue ----
    float bx = bias ? bias[f0+0] : 0.0f;
    float by = bias ? bias[f0+1] : 0.0f;
    float bz = bias ? bias[f0+2] : 0.0f;
    float bw = bias ? bias[f0+3] : 0.0f;
    #pragma unroll
    for (int ip = 0; ip < 2; ip++) {
        float2 p0 = unpk(acc[ip][0]);
        float2 p1 = unpk(acc[ip][1]);
        float2 p2 = unpk(acc[ip][2]);
        float2 p3 = unpk(acc[ip][3]);
        #pragma unroll
        for (int half = 0; half < 2; half++) {
            int row = base + r0 + 2*ip + half;
            if (row >= nrows) continue;
            float4 v;
            if (half == 0) { v.x = p0.x; v.y = p1.x; v.z = p2.x; v.w = p3.x; }
            else           { v.x = p0.y; v.y = p1.y; v.z = p2.y; v.w = p3.y; }
            v.x += bx; v.y += by; v.z += bz; v.w += bw;
            if (do_silu) {
                v.x = silu_f(v.x); v.y = silu_f(v.y);
                v.z = silu_f(v.z); v.w = silu_f(v.w);
            }
            if (res) {
                float4 rv = *(const float4*)&res[(size_t)row*96 + f0];
                v.x += rv.x; v.y += rv.y; v.z += rv.z; v.w += rv.w;
            }
            *(float4*)&out[(size_t)row*96 + f0] = v;
        }
    }
}

// ---------------- fused edge message + aggregation (FFMA2, 128-edge tile) ----
// t = silu(A[send] + B[rec] + dist*w_d + b1); m = silu(t@W2 + b2); aggr[rec]+=m
__global__ void __launch_bounds__(384, 2)
edge_msg(const float* __restrict__ wl, const float* __restrict__ b1,
         const float* __restrict__ W2, const float* __restrict__ b2)
{
    extern __shared__ float sm[];
    float* W2s = sm;                 // 9216
    float* tT  = W2s + 9216;         // 96*128 transposed: tT[k*128 + e]
    float* b1s = tT + 12288;         // 96
    float* b2s = b1s + 96;           // 96
    float* wls = b2s + 96;           // 96
    float* de  = wls + 96;           // 128
    int*   se  = (int*)(de + 128);   // 128
    int*   re  = se + 128;           // 128

    const int tid  = threadIdx.y * 24 + threadIdx.x;
    const int base = blockIdx.x * ETILE;

    for (int idx = tid; idx < 9216; idx += 384) W2s[idx] = W2[idx];
    if (tid < 96) { b1s[tid] = b1[tid]; b2s[tid] = b2[tid]; wls[tid] = wl[tid]; }
    else if (tid < 224) {
        int j = tid - 96; int e = base + j;
        se[j] = g_send[e];
        re[j] = g_rec[e];
        de[j] = g_dist[e];
    }
    __syncthreads();

    // phase 1: build t (transposed) — vector gathers, conflict-free STS
    #pragma unroll
    for (int it = 0; it < 8; it++) {      // 24 chunks * 128 edges / 384 thr
        int idx = it * 384 + tid;
        int k4 = idx >> 7;
        int e  = idx & 127;
        int s = se[e], r = re[e];
        float  d  = de[e];
        float4 a  = *(const float4*)&g_A[(size_t)s*96 + k4*4];
        float4 b  = *(const float4*)&g_B[(size_t)r*96 + k4*4];
        float4 w4 = *(const float4*)&wls[k4*4];
        float4 c4 = *(const float4*)&b1s[k4*4];
        tT[(k4*4+0)*128 + e] = silu_f(a.x + b.x + d*w4.x + c4.x);
        tT[(k4*4+1)*128 + e] = silu_f(a.y + b.y + d*w4.y + c4.y);
        tT[(k4*4+2)*128 + e] = silu_f(a.z + b.z + d*w4.z + c4.z);
        tT[(k4*4+3)*128 + e] = silu_f(a.w + b.w + d*w4.w + c4.w);
    }
    __syncthreads();

    // phase 2: m = t @ W2 — 8-row x 4-col tiles, FFMA2
    const int f0 = threadIdx.x * 4;
    const int r0 = threadIdx.y * 8;
    ull acc[4][4];
    #pragma unroll
    for (int i = 0; i < 4; i++)
        #pragma unroll
        for (int c = 0; c < 4; c++) acc[i][c] = 0ull;

    #pragma unroll 2
    for (int k = 0; k < 96; k++) {
        float4 w = *(const float4*)&W2s[k*96 + f0];
        ull w0 = bc2(w.x), w1 = bc2(w.y), w2 = bc2(w.z), w3 = bc2(w.w);
        const ull* tp = (const ull*)&tT[k*128 + r0];
        #pragma unroll
        for (int ip = 0; ip < 4; ip++) {
            ull t2 = tp[ip];
            acc[ip][0] = ffma2(t2, w0, acc[ip][0]);
            acc[ip][1] = ffma2(t2, w1, acc[ip][1]);
            acc[ip][2] = ffma2(t2, w2, acc[ip][2]);
            acc[ip][3] = ffma2(t2, w3, acc[ip][3]);
        }
    }

    // epilogue: silu + scatter-add
    float bx = b2s[f0+0], by = b2s[f0+1], bz = b2s[f0+2], bw = b2s[f0+3];
    #pragma unroll
    for (int ip = 0; ip < 4; ip++) {
        float2 p0 = unpk(acc[ip][0]);
        float2 p1 = unpk(acc[ip][1]);
        float2 p2 = unpk(acc[ip][2]);
        float2 p3 = unpk(acc[ip][3]);
        int e0 = r0 + 2*ip;
        float4 m;
        m.x = silu_f(p0.x + bx); m.y = silu_f(p1.x + by);
        m.z = silu_f(p2.x + bz); m.w = silu_f(p3.x + bw);
        red_add_v4(&g_aggr[(size_t)re[e0]*96 + f0], m);
        m.x = silu_f(p0.y + bx); m.y = silu_f(p1.y + by);
        m.z = silu_f(p2.y + bz); m.w = silu_f(p3.y + bw);
        red_add_v4(&g_aggr[(size_t)re[e0+1]*96 + f0], m);
    }
}

// ---------------- zero / pooling / readout ----------------------------------
__global__ void zero_aggr_kernel() {
    int i = blockIdx.x * 1024 + threadIdx.x;
    if (i < N_NODES * HDIM) g_aggr[i] = 0.0f;
}
__global__ void zero_pooled_kernel() {
    int i = blockIdx.x * 256 + threadIdx.x;
    if (i < N_GRAPHS * HDIM) g_pooled[i] = 0.0f;
}

__global__ void pool_kernel(const float* __restrict__ h2, const int* __restrict__ braw) {
    __shared__ int s_is64;
    if (threadIdx.x == 0) {
        s_is64 = ((braw[N_NODES-1] | braw[N_NODES-3] |
                   braw[N_NODES-5] | braw[N_NODES-7]) == 0) ? 1 : 0;
    }
    __syncthreads();
    int idx = blockIdx.x * blockDim.x + threadIdx.x;
    if (idx >= N_NODES * 24) return;
    int n = idx / 24, j = idx - n * 24;
    int g = s_is64 ? (int)((const long long*)braw)[n] : braw[n];
    float4 v = *(const float4*)&h2[(size_t)n*96 + j*4];
    red_add_v4(&g_pooled[g*96 + j*4], v);
}

__global__ void readout_kernel(const float* __restrict__ w1, const float* __restrict__ b1,
                               const float* __restrict__ w2, const float* __restrict__ b2,
                               float* __restrict__ out)
{
    __shared__ float p_s[96];
    __shared__ float t_s[96];
    int g = blockIdx.x, f = threadIdx.x;
    p_s[f] = g_pooled[g*96 + f];
    __syncthreads();
    float a = b1[f];
    #pragma unroll 8
    for (int k = 0; k < 96; k++) a += p_s[k] * w1[k*96 + f];
    t_s[f] = silu_f(a) * w2[f];
    __syncthreads();
    if (f < 32) {
        float sum = t_s[f] + t_s[f+32] + t_s[f+64];
        #pragma unroll
        for (int o = 16; o > 0; o >>= 1) sum += __shfl_down_sync(0xffffffffu, sum, o);
        if (f == 0) out[g] = sum + b2[0];
    }
}

// ---------------- host launcher ----------------------------------------------
static void launch_node(const float* in1, int K1, const float* W1,
                        const float* in2, int K2, const float* W2,
                        const float* bias, const float* res,
                        float* out, int do_silu)
{
    int K1p = (K1 + 3) & ~3;
    int K2p = (K2 + 3) & ~3;
    int Kmax = K1p > K2p ? K1p : K2p;
    size_t smem = (size_t)(K1p + K2p) * 96 * 4 + (size_t)64 * Kmax * 4;
    dim3 tb(24, 16);
    int blocks = (N_NODES + 63) / 64;
    node_mlp<<<blocks, tb, smem>>>(in1, K1, W1, in2, K2, W2, bias, res, out, N_NODES, do_silu);
}

extern "C" void kernel_launch(void* const* d_in, const int* in_sizes, int n_in,
                              void* d_out, int out_size)
{
    const float* x    = (const float*)d_in[0];
    const float* pos  = (const float*)d_in[1];
    const float* pe   = (const float*)d_in[2];
    const int*   eraw = (const int*)d_in[3];
    const int*   braw = (const int*)d_in[4];
    const float* ew1  = (const float*)d_in[5];
    const float* eb1  = (const float*)d_in[6];
    const float* ew2  = (const float*)d_in[7];
    const float* eb2  = (const float*)d_in[8];
    const float* mw1  = (const float*)d_in[9];
    const float* mb1  = (const float*)d_in[10];
    const float* mw2  = (const float*)d_in[11];
    const float* mb2  = (const float*)d_in[12];
    const float* uw1  = (const float*)d_in[13];
    const float* ub1  = (const float*)d_in[14];
    const float* uw2  = (const float*)d_in[15];
    const float* ub2  = (const float*)d_in[16];
    const float* pw1  = (const float*)d_in[17];
    const float* pb1  = (const float*)d_in[18];
    const float* pw2  = (const float*)d_in[19];
    const float* pb2  = (const float*)d_in[20];
    const float* rw1  = (const float*)d_in[21];
    const float* rb1  = (const float*)d_in[22];
    const float* rw2  = (const float*)d_in[23];
    const float* rb2  = (const float*)d_in[24];
    float* out = (float*)d_out;

    float *h_, *A_, *B_, *aggr_, *u_;
    cudaGetSymbolAddress((void**)&h_,    g_h);
    cudaGetSymbolAddress((void**)&A_,    g_A);
    cudaGetSymbolAddress((void**)&B_,    g_B);
    cudaGetSymbolAddress((void**)&aggr_, g_aggr);
    cudaGetSymbolAddress((void**)&u_,    g_u);

    cudaFuncSetAttribute((const void*)node_mlp,
                         cudaFuncAttributeMaxDynamicSharedMemorySize, 102400);
    cudaFuncSetAttribute((const void*)edge_msg,
                         cudaFuncAttributeMaxDynamicSharedMemorySize, 92160);

    // smem: 9216 + 12288 + 96*3 + 128 + 128 + 128 floats/ints = 22176 * 4 B
    const size_t edge_smem = 22176u * 4u;

    edge_prep<<<(N_EDGES + 255) / 256, 256>>>(eraw, pos);

    // embed: h = silu([x,pe]@W1+b1)@W2+b2
    launch_node(x, NUM_IN, ew1, pe, PE_DIM, ew1 + NUM_IN * 96, eb1, nullptr, u_, 1);
    launch_node(u_, 96, ew2, nullptr, 0, nullptr, eb2, nullptr, h_, 0);

    dim3 tb(24, 16);
    for (int l = 0; l < N_LAYERS; l++) {
        const float* mw1l = mw1 + (size_t)l * 193 * 96;
        const float* mb1l = mb1 + l * 96;
        const float* mw2l = mw2 + (size_t)l * 96 * 96;
        const float* mb2l = mb2 + l * 96;
        const float* uw1l = uw1 + (size_t)l * 192 * 96;
        const float* ub1l = ub1 + l * 96;
        const float* uw2l = uw2 + (size_t)l * 96 * 96;
        const float* ub2l = ub2 + l * 96;

        // A = h @ W1[0:96], B = h @ W1[96:192]
        launch_node(h_, 96, mw1l,            nullptr, 0, nullptr, nullptr, nullptr, A_, 0);
        launch_node(h_, 96, mw1l + 96 * 96,  nullptr, 0, nullptr, nullptr, nullptr, B_, 0);

        zero_aggr_kernel<<<(N_NODES * HDIM + 1023) / 1024, 1024>>>();
        edge_msg<<<N_EDGES / ETILE, tb, edge_smem>>>(mw1l + 192 * 96, mb1l, mw2l, mb2l);

        // u = silu(h@U1a + aggr@U1b + b1);  h = h + (u@U2 + b2)
        launch_node(h_, 96, uw1l, aggr_, 96, uw1l + 96 * 96, ub1l, nullptr, u_, 1);
        launch_node(u_, 96, uw2l, nullptr, 0, nullptr, ub2l, h_, h_, 0);
    }

    // pre-MLP -> h2 (stored in g_A)
    launch_node(h_, 96, pw1, nullptr, 0, nullptr, pb1, nullptr, u_, 1);
    launch_node(u_, 96, pw2, nullptr, 0, nullptr, pb2, nullptr, A_, 0);

    zero_pooled_kernel<<<(N_GRAPHS * HDIM + 255) / 256, 256>>>();
    pool_kernel<<<(N_NODES * 24 + 255) / 256, 256>>>(A_, braw);
    readout_kernel<<<N_GRAPHS, 96>>>(rw1, rb1, rw2, rb2, out);
}